// round 10
// baseline (speedup 1.0000x reference)
#include <cuda_runtime.h>
#include <cuda_bf16.h>
#include <cstdint>

#define KDIM 4096
#define RDIM 64
#define NWID 80
#define CDIM 320
#define KC 128                  // k per chunk
#define NCHUNK (KDIM / KC)      // 32
#define ASTRIDE 36              // A-smem row stride in floats (32 + 4 pad) = 144 B
#define CHUNK_TX (KC * 128)     // bytes per chunk: 128 rows x 128 B

// Group tables: pairs of c-indices sharing the same wid (c1 = -1 for singleton).
__device__ int g_gc0[CDIM];
__device__ int g_gc1[CDIM];
__device__ int g_order[CDIM];
__device__ int g_ngroups;

// Deterministic stable counting sort of c by wid, then pair same-wid c's.
__global__ void prep_groups(const int* __restrict__ wids, int C)
{
    __shared__ int sw[CDIM];
    __shared__ int cnt[NWID];
    __shared__ int start[NWID];
    const int t = threadIdx.x;

    if (t < C)    sw[t]  = wids[t];
    if (t < NWID) cnt[t] = 0;
    __syncthreads();
    if (t < C) atomicAdd(&cnt[sw[t]], 1);
    __syncthreads();
    if (t == 0) {
        int a = 0;
        for (int i = 0; i < NWID; ++i) { start[i] = a; a += cnt[i]; }
    }
    __syncthreads();
    if (t < C) {
        const int w = sw[t];
        int r = 0;
        for (int u = 0; u < t; ++u) r += (sw[u] == w);   // stable rank
        g_order[start[w] + r] = t;
    }
    __syncthreads();
    if (t == 0) {
        int g = 0;
        for (int w = 0; w < NWID; ++w) {
            const int s0 = start[w], n = cnt[w];
            int i = 0;
            for (; i + 1 < n; i += 2) {
                g_gc0[g] = g_order[s0 + i];
                g_gc1[g] = g_order[s0 + i + 1];
                ++g;
            }
            if (i < n) { g_gc0[g] = g_order[s0 + i]; g_gc1[g] = -1; ++g; }
        }
        g_ngroups = g;
    }
}

// out[c,r] = sum_k x[xids[c*64+r], k] * A[wids[c], k, r]
//
// Block = (group of <=2 same-wid c's, r-half). 512 threads = 16 warps.
//   warps 0-7 -> c0 quads, warps 8-15 -> c1 quads (idle if singleton).
//   warp quad q owns r0 = rh*32+4q; lane s owns k = {s, s+32, s+64, s+96} per chunk.
// A staged ONCE per chunk for both c's: per-row cp.async.bulk (TMA path) into
// double-buffered padded smem (stride 36 floats -> conflict-free LDS.128).
// One __syncthreads per chunk = buffer-empty condition for the refill.
__global__ void __launch_bounds__(512, 2) lora_gather_dot_kernel(
    const float* __restrict__ x,
    const int*   __restrict__ xids,
    const int*   __restrict__ wids,
    const float* __restrict__ A,
    float*       __restrict__ out)
{
    if ((int)blockIdx.x >= g_ngroups) return;   // uniform per block

    __shared__ __align__(128) float as[2][KC * ASTRIDE];   // 2 x 18432 B
    __shared__ __align__(8) unsigned long long mbar[2];

    const int g   = blockIdx.x;
    const int rh  = blockIdx.y;
    const int tid = threadIdx.x;
    const int wrp = tid >> 5;
    const int s   = tid & 31;
    const int q   = wrp & 7;         // r-quad within the c
    const int which = wrp >> 3;      // 0 -> c0, 1 -> c1

    const int c0 = g_gc0[g];
    const int c1 = g_gc1[g];
    const bool active = (which == 0) || (c1 >= 0);
    const int c = (which && c1 >= 0) ? c1 : c0;

    const int wid   = wids[c0];
    const int rbase = rh * 32;
    const int r0    = rbase + 4 * q;

    // x row pointers for this warp's 4 tokens, pre-offset by lane s
    const float *xp0, *xp1, *xp2, *xp3;
    {
        const int base = c * RDIM + r0;
        const int o0 = active ? xids[base + 0] * KDIM : 0;
        const int o1 = active ? xids[base + 1] * KDIM : 0;
        const int o2 = active ? xids[base + 2] * KDIM : 0;
        const int o3 = active ? xids[base + 3] * KDIM : 0;
        xp0 = x + o0 + s; xp1 = x + o1 + s; xp2 = x + o2 + s; xp3 = x + o3 + s;
    }

    // A[w][k][r]; this block's 32-r window (gmem rows: 128 B @ 256 B stride)
    const float* __restrict__ Ab = A + (size_t)wid * KDIM * RDIM + rbase;

    uint32_t as_u32[2], mb_u32[2];
    {
        uint32_t a0;
        asm("{ .reg .u64 t; cvta.to.shared.u64 t, %1; cvt.u32.u64 %0, t; }"
            : "=r"(a0) : "l"(&as[0][0]));
        as_u32[0] = a0;
        asm("{ .reg .u64 t; cvta.to.shared.u64 t, %1; cvt.u32.u64 %0, t; }"
            : "=r"(a0) : "l"(&as[1][0]));
        as_u32[1] = a0;
        asm("{ .reg .u64 t; cvta.to.shared.u64 t, %1; cvt.u32.u64 %0, t; }"
            : "=r"(a0) : "l"(&mbar[0]));
        mb_u32[0] = a0;
        mb_u32[1] = a0 + 8;
    }

    if (tid == 0) {
        asm volatile("mbarrier.init.shared::cta.b64 [%0], 1;" :: "r"(mb_u32[0]) : "memory");
        asm volatile("mbarrier.init.shared::cta.b64 [%0], 1;" :: "r"(mb_u32[1]) : "memory");
    }
    __syncthreads();

    // per-copy-thread source pointer (advances 32 KB per chunk) and dst addrs
    const float* srcp = Ab + (size_t)tid * RDIM;
    const uint32_t dstA = as_u32[0] + tid * (ASTRIDE * 4);
    const uint32_t dstB = as_u32[1] + tid * (ASTRIDE * 4);

    // ---- prologue: chunk 0 -> buf 0 ----
    if (tid == 0) {
        asm volatile("mbarrier.arrive.expect_tx.shared::cta.b64 _, [%0], %1;"
                     :: "r"(mb_u32[0]), "r"((uint32_t)CHUNK_TX) : "memory");
    }
    if (tid < KC) {
        asm volatile(
            "cp.async.bulk.shared::cluster.global.mbarrier::complete_tx::bytes "
            "[%0], [%1], %2, [%3];"
            :: "r"(dstA), "l"(srcp), "r"(128u), "r"(mb_u32[0]) : "memory");
    }
    srcp += KC * RDIM;

    float acc0 = 0.f, acc1 = 0.f, acc2 = 0.f, acc3 = 0.f;
    int ph0 = 0, ph1 = 0;

    for (int ch = 0; ch < NCHUNK; ++ch) {
        const int b = ch & 1;

        // refill the other buffer (its readers finished before last iter's sync)
        if (ch + 1 < NCHUNK) {
            const int nb = b ^ 1;
            if (tid == 0) {
                asm volatile("mbarrier.arrive.expect_tx.shared::cta.b64 _, [%0], %1;"
                             :: "r"(mb_u32[nb]), "r"((uint32_t)CHUNK_TX) : "memory");
            }
            if (tid < KC) {
                asm volatile(
                    "cp.async.bulk.shared::cluster.global.mbarrier::complete_tx::bytes "
                    "[%0], [%1], %2, [%3];"
                    :: "r"(nb ? dstB : dstA), "l"(srcp), "r"(128u), "r"(mb_u32[nb])
                    : "memory");
            }
            srcp += KC * RDIM;
        }

        // wait for this chunk (acquire orders the LDS below; HW-sleep wait)
        {
            const uint32_t mb = mb_u32[b];
            const uint32_t ph = (uint32_t)(b ? ph1 : ph0);
            uint32_t done;
            do {
                asm volatile(
                    "{ .reg .pred p; "
                    "mbarrier.try_wait.parity.acquire.cta.shared::cta.b64 p, [%1], %2, 0x989680; "
                    "selp.b32 %0, 1, 0, p; }"
                    : "=r"(done) : "r"(mb), "r"(ph) : "memory");
            } while (!done);
            if (b) ph1 ^= 1; else ph0 ^= 1;
        }

        if (active) {
            const float* asb = &as[b][0];
            #pragma unroll
            for (int i = 0; i < 4; ++i) {
                const int kl = s + 32 * i;
                const float4 av =
                    *reinterpret_cast<const float4*>(&asb[kl * ASTRIDE + 4 * q]);
                acc0 += xp0[32 * i] * av.x;
                acc1 += xp1[32 * i] * av.y;
                acc2 += xp2[32 * i] * av.z;
                acc3 += xp3[32 * i] * av.w;
            }
        }
        xp0 += KC; xp1 += KC; xp2 += KC; xp3 += KC;

        if (ch + 1 < NCHUNK) __syncthreads();   // readers of buf done -> refill safe
    }

    // reduce over the 32 lanes (k) within each warp
    #pragma unroll
    for (int off = 16; off > 0; off >>= 1) {
        acc0 += __shfl_xor_sync(0xffffffffu, acc0, off);
        acc1 += __shfl_xor_sync(0xffffffffu, acc1, off);
        acc2 += __shfl_xor_sync(0xffffffffu, acc2, off);
        acc3 += __shfl_xor_sync(0xffffffffu, acc3, off);
    }
    if (s == 0 && active) {
        float4 o = make_float4(acc0, acc1, acc2, acc3);
        *reinterpret_cast<float4*>(&out[c * RDIM + r0]) = o;
    }
}

extern "C" void kernel_launch(void* const* d_in, const int* in_sizes, int n_in,
                              void* d_out, int out_size)
{
    const float* x    = (const float*)d_in[0];   // [512,1,4096] f32
    const int*   xids = (const int*)  d_in[1];   // [20480] i32
    const int*   wids = (const int*)  d_in[2];   // [320] i32
    const float* A    = (const float*)d_in[3];   // [80,4096,64] f32
    float*       out  = (float*)d_out;           // [320,1,64] f32

    const int C = in_sizes[2];                   // COMBINED_BS (320)
    prep_groups<<<1, 512>>>(wids, C);
    dim3 grid(CDIM, 2);                          // (max groups, r-half); extras exit
    lora_gather_dot_kernel<<<grid, 512>>>(x, xids, wids, A, out);
}

// round 12
// speedup vs baseline: 1.6284x; 1.6284x over previous
#include <cuda_runtime.h>
#include <cuda_bf16.h>
#include <cstdint>

#define KDIM 4096
#define RDIM 64
#define NWID 80
#define CDIM 320
#define KC 128                  // k per chunk
#define NCHUNK (KDIM / KC)      // 32
#define ASTRIDE 36              // A-smem row stride in floats (32 + 4 pad) = 144 B
#define CHUNK_TX (KC * 128)     // bytes per chunk: 128 rows x 128 B

// Pair tables: groups of <=2 c-indices sharing a wid (c1 = -1 for singleton).
__device__ int g_gc0[CDIM];
__device__ int g_gc1[CDIM];
__device__ int g_ngroups;

// Fully parallel pairing. Rank within wid via atomicAdd (order nondeterministic,
// but each c's computation/output is independent of its partner -> output
// deterministic). ~1-2 us.
__global__ void prep_groups(const int* __restrict__ wids, int C)
{
    __shared__ int cnt[NWID];
    __shared__ int gbase[NWID];
    const int t = threadIdx.x;

    if (t < NWID) cnt[t] = 0;
    __syncthreads();
    int w = 0, r = 0;
    if (t < C) { w = wids[t]; r = atomicAdd(&cnt[w], 1); }
    __syncthreads();
    if (t == 0) {
        int g = 0;
        for (int i = 0; i < NWID; ++i) { gbase[i] = g; g += (cnt[i] + 1) >> 1; }
        g_ngroups = g;
    }
    __syncthreads();
    if (t < C) {
        const int n   = cnt[w];
        const int grp = gbase[w] + (r >> 1);
        if (r & 1) {
            g_gc1[grp] = t;
        } else {
            g_gc0[grp] = t;
            if (r == n - 1) g_gc1[grp] = -1;   // odd tail -> singleton
        }
    }
}

// out[c,r] = sum_k x[xids[c*64+r], k] * A[wids[c], k, r]
//
// Block = (pair group, r-half). 256 threads = 8 warps (R7 execution shape).
//   warp q owns r-quad r0 = rh*32 + 4q; lane s owns k = {s,s+32,s+64,s+96}/chunk.
//   Each thread accumulates BOTH c0 and c1 against the same smem A value.
// A staged once per chunk for the pair: per-row cp.async.bulk (TMA path) into
// double-buffered padded smem (stride 36 floats -> conflict-free LDS.128).
// One __syncthreads per chunk = buffer-empty condition for the refill.
__global__ void __launch_bounds__(256, 4) lora_gather_dot_kernel(
    const float* __restrict__ x,
    const int*   __restrict__ xids,
    const int*   __restrict__ wids,
    const float* __restrict__ A,
    float*       __restrict__ out)
{
    if ((int)blockIdx.x >= g_ngroups) return;   // uniform per block

    __shared__ __align__(128) float as[2][KC * ASTRIDE];   // 2 x 18432 B
    __shared__ __align__(8) unsigned long long mbar[2];

    const int g   = blockIdx.x;
    const int rh  = blockIdx.y;
    const int tid = threadIdx.x;
    const int q   = tid >> 5;
    const int s   = tid & 31;

    const int c0   = g_gc0[g];
    const int c1   = g_gc1[g];
    const bool dual = (c1 >= 0);

    const int wid   = wids[c0];
    const int rbase = rh * 32;
    const int r0    = rbase + 4 * q;

    // x row pointers (pre-offset by lane s) for c0's and c1's tokens
    const float *xa0, *xa1, *xa2, *xa3, *xb0, *xb1, *xb2, *xb3;
    {
        const int baseA = c0 * RDIM + r0;
        xa0 = x + xids[baseA + 0] * KDIM + s;
        xa1 = x + xids[baseA + 1] * KDIM + s;
        xa2 = x + xids[baseA + 2] * KDIM + s;
        xa3 = x + xids[baseA + 3] * KDIM + s;
        const int baseB = (dual ? c1 : c0) * RDIM + r0;
        xb0 = x + xids[baseB + 0] * KDIM + s;
        xb1 = x + xids[baseB + 1] * KDIM + s;
        xb2 = x + xids[baseB + 2] * KDIM + s;
        xb3 = x + xids[baseB + 3] * KDIM + s;
    }

    // A[w][k][r]; this block's 32-r window (gmem rows: 128 B @ 256 B stride)
    const float* __restrict__ Ab = A + (size_t)wid * KDIM * RDIM + rbase;

    uint32_t as_u32[2], mb_u32[2];
    {
        uint32_t a0;
        asm("{ .reg .u64 t; cvta.to.shared.u64 t, %1; cvt.u32.u64 %0, t; }"
            : "=r"(a0) : "l"(&as[0][0]));
        as_u32[0] = a0;
        asm("{ .reg .u64 t; cvta.to.shared.u64 t, %1; cvt.u32.u64 %0, t; }"
            : "=r"(a0) : "l"(&as[1][0]));
        as_u32[1] = a0;
        asm("{ .reg .u64 t; cvta.to.shared.u64 t, %1; cvt.u32.u64 %0, t; }"
            : "=r"(a0) : "l"(&mbar[0]));
        mb_u32[0] = a0;
        mb_u32[1] = a0 + 8;
    }

    if (tid == 0) {
        asm volatile("mbarrier.init.shared::cta.b64 [%0], 1;" :: "r"(mb_u32[0]) : "memory");
        asm volatile("mbarrier.init.shared::cta.b64 [%0], 1;" :: "r"(mb_u32[1]) : "memory");
    }
    __syncthreads();

    const float* srcp = Ab + (size_t)tid * RDIM;     // +32 KB per chunk
    const uint32_t dstA = as_u32[0] + tid * (ASTRIDE * 4);
    const uint32_t dstB = as_u32[1] + tid * (ASTRIDE * 4);

    // ---- prologue: chunk 0 -> buf 0 ----
    if (tid == 0) {
        asm volatile("mbarrier.arrive.expect_tx.shared::cta.b64 _, [%0], %1;"
                     :: "r"(mb_u32[0]), "r"((uint32_t)CHUNK_TX) : "memory");
    }
    if (tid < KC) {
        asm volatile(
            "cp.async.bulk.shared::cluster.global.mbarrier::complete_tx::bytes "
            "[%0], [%1], %2, [%3];"
            :: "r"(dstA), "l"(srcp), "r"(128u), "r"(mb_u32[0]) : "memory");
    }
    srcp += KC * RDIM;

    float a0 = 0.f, a1 = 0.f, a2 = 0.f, a3 = 0.f;
    float b0 = 0.f, b1 = 0.f, b2 = 0.f, b3 = 0.f;
    int ph0 = 0, ph1 = 0;

    for (int ch = 0; ch < NCHUNK; ++ch) {
        const int b = ch & 1;

        // refill the other buffer (its readers finished before last iter's sync)
        if (ch + 1 < NCHUNK) {
            const int nb = b ^ 1;
            if (tid == 0) {
                asm volatile("mbarrier.arrive.expect_tx.shared::cta.b64 _, [%0], %1;"
                             :: "r"(mb_u32[nb]), "r"((uint32_t)CHUNK_TX) : "memory");
            }
            if (tid < KC) {
                asm volatile(
                    "cp.async.bulk.shared::cluster.global.mbarrier::complete_tx::bytes "
                    "[%0], [%1], %2, [%3];"
                    :: "r"(nb ? dstB : dstA), "l"(srcp), "r"(128u), "r"(mb_u32[nb])
                    : "memory");
            }
            srcp += KC * RDIM;
        }

        // wait for this chunk (acquire orders the LDS below)
        {
            const uint32_t mb = mb_u32[b];
            const uint32_t ph = (uint32_t)(b ? ph1 : ph0);
            uint32_t done;
            do {
                asm volatile(
                    "{ .reg .pred p; "
                    "mbarrier.try_wait.parity.acquire.cta.shared::cta.b64 p, [%1], %2, 0x989680; "
                    "selp.b32 %0, 1, 0, p; }"
                    : "=r"(done) : "r"(mb), "r"(ph) : "memory");
            } while (!done);
            if (b) ph1 ^= 1; else ph0 ^= 1;
        }

        const float* asb = &as[b][0];
        if (dual) {
            #pragma unroll
            for (int i = 0; i < 4; ++i) {
                const int kl = s + 32 * i;
                const float4 av =
                    *reinterpret_cast<const float4*>(&asb[kl * ASTRIDE + 4 * q]);
                a0 += xa0[32 * i] * av.x;
                a1 += xa1[32 * i] * av.y;
                a2 += xa2[32 * i] * av.z;
                a3 += xa3[32 * i] * av.w;
                b0 += xb0[32 * i] * av.x;
                b1 += xb1[32 * i] * av.y;
                b2 += xb2[32 * i] * av.z;
                b3 += xb3[32 * i] * av.w;
            }
        } else {
            #pragma unroll
            for (int i = 0; i < 4; ++i) {
                const int kl = s + 32 * i;
                const float4 av =
                    *reinterpret_cast<const float4*>(&asb[kl * ASTRIDE + 4 * q]);
                a0 += xa0[32 * i] * av.x;
                a1 += xa1[32 * i] * av.y;
                a2 += xa2[32 * i] * av.z;
                a3 += xa3[32 * i] * av.w;
            }
        }
        xa0 += KC; xa1 += KC; xa2 += KC; xa3 += KC;
        xb0 += KC; xb1 += KC; xb2 += KC; xb3 += KC;

        if (ch + 1 < NCHUNK) __syncthreads();   // readers done -> refill safe
    }

    // reduce over the 32 lanes (k) within each warp
    #pragma unroll
    for (int off = 16; off > 0; off >>= 1) {
        a0 += __shfl_xor_sync(0xffffffffu, a0, off);
        a1 += __shfl_xor_sync(0xffffffffu, a1, off);
        a2 += __shfl_xor_sync(0xffffffffu, a2, off);
        a3 += __shfl_xor_sync(0xffffffffu, a3, off);
        b0 += __shfl_xor_sync(0xffffffffu, b0, off);
        b1 += __shfl_xor_sync(0xffffffffu, b1, off);
        b2 += __shfl_xor_sync(0xffffffffu, b2, off);
        b3 += __shfl_xor_sync(0xffffffffu, b3, off);
    }
    if (s == 0) {
        *reinterpret_cast<float4*>(&out[c0 * RDIM + r0]) =
            make_float4(a0, a1, a2, a3);
        if (dual)
            *reinterpret_cast<float4*>(&out[c1 * RDIM + r0]) =
                make_float4(b0, b1, b2, b3);
    }
}

extern "C" void kernel_launch(void* const* d_in, const int* in_sizes, int n_in,
                              void* d_out, int out_size)
{
    const float* x    = (const float*)d_in[0];   // [512,1,4096] f32
    const int*   xids = (const int*)  d_in[1];   // [20480] i32
    const int*   wids = (const int*)  d_in[2];   // [320] i32
    const float* A    = (const float*)d_in[3];   // [80,4096,64] f32
    float*       out  = (float*)d_out;           // [320,1,64] f32

    const int C = in_sizes[2];                   // COMBINED_BS (320)
    prep_groups<<<1, CDIM>>>(wids, C);
    dim3 grid(CDIM, 2);                          // (max groups, r-half); extras exit
    lora_gather_dot_kernel<<<grid, 256>>>(x, xids, wids, A, out);
}

// round 14
// speedup vs baseline: 1.6860x; 1.0354x over previous
#include <cuda_runtime.h>
#include <cuda_bf16.h>
#include <cstdint>

#define KDIM 4096
#define KHALF (KDIM / 2)        // 2048 k per block (k-split)
#define RDIM 64
#define NWID 80
#define CDIM 320
#define KC 128                  // k per chunk
#define NCH (KHALF / KC)        // 16 chunks per block
#define ASTRIDE 36              // A-smem row stride in floats (32 + 4 pad) = 144 B
#define CHUNK_TX (KC * 128)     // bytes per chunk: 128 rows x 128 B

// Pair tables: groups of <=2 c-indices sharing a wid (c1 = -1 for singleton).
__device__ int g_gc0[CDIM];
__device__ int g_gc1[CDIM];
__device__ int g_ngroups;

// Fully parallel pairing. Rank within wid via atomicAdd (pairing order
// nondeterministic, but each c's result is independent of its partner ->
// output deterministic).
__global__ void prep_groups(const int* __restrict__ wids, int C)
{
    __shared__ int cnt[NWID];
    __shared__ int gbase[NWID];
    const int t = threadIdx.x;

    if (t < NWID) cnt[t] = 0;
    __syncthreads();
    int w = 0, r = 0;
    if (t < C) { w = wids[t]; r = atomicAdd(&cnt[w], 1); }
    __syncthreads();
    if (t == 0) {
        int g = 0;
        for (int i = 0; i < NWID; ++i) { gbase[i] = g; g += (cnt[i] + 1) >> 1; }
        g_ngroups = g;
    }
    __syncthreads();
    if (t < C) {
        const int n   = cnt[w];
        const int grp = gbase[w] + (r >> 1);
        if (r & 1) {
            g_gc1[grp] = t;
        } else {
            g_gc0[grp] = t;
            if (r == n - 1) g_gc1[grp] = -1;   // odd tail -> singleton
        }
    }
}

// out is poisoned 0xAA by the harness; k-split partials are atomicAdd'ed.
__global__ void zero_out(float* __restrict__ out)
{
    out[blockIdx.x * 256 + threadIdx.x] = 0.f;
}

// out[c,r] = sum_k x[xids[c*64+r], k] * A[wids[c], k, r]
//
// Block = (pair group, r-half, k-half). 256 threads = 8 warps.
//   warp q owns r-quad r0 = rh*32 + 4q; lane s owns k = {s,s+32,s+64,s+96}/chunk.
//   Each thread accumulates BOTH c0 and c1 against the same smem A value.
// k-split (grid.z=2) is traffic-neutral (A/x reads partition in k) and restores
// ~720 active blocks (~4.9/SM) -> latency hiding that pairing alone destroyed.
// Each output element receives exactly 2 atomicAdd partials: a+b commutative in
// IEEE -> bitwise deterministic.
// A staged once per chunk for the pair: per-row cp.async.bulk (TMA path) into
// double-buffered padded smem (stride 36 floats -> conflict-free LDS.128).
// One __syncthreads per chunk = buffer-empty condition for the refill.
__global__ void __launch_bounds__(256, 4) lora_gather_dot_kernel(
    const float* __restrict__ x,
    const int*   __restrict__ xids,
    const int*   __restrict__ wids,
    const float* __restrict__ A,
    float*       __restrict__ out)
{
    if ((int)blockIdx.x >= g_ngroups) return;   // uniform per block

    __shared__ __align__(128) float as[2][KC * ASTRIDE];   // 2 x 18432 B
    __shared__ __align__(8) unsigned long long mbar[2];

    const int g   = blockIdx.x;
    const int rh  = blockIdx.y;
    const int kz  = blockIdx.z;          // k-half
    const int tid = threadIdx.x;
    const int q   = tid >> 5;
    const int s   = tid & 31;

    const int c0   = g_gc0[g];
    const int c1   = g_gc1[g];
    const bool dual = (c1 >= 0);

    const int wid   = wids[c0];
    const int rbase = rh * 32;
    const int r0    = rbase + 4 * q;
    const int kbase = kz * KHALF;

    // x row pointers (pre-offset by lane s and k-half) for c0's and c1's tokens
    const float *xa0, *xa1, *xa2, *xa3, *xb0, *xb1, *xb2, *xb3;
    {
        const int baseA = c0 * RDIM + r0;
        xa0 = x + xids[baseA + 0] * KDIM + kbase + s;
        xa1 = x + xids[baseA + 1] * KDIM + kbase + s;
        xa2 = x + xids[baseA + 2] * KDIM + kbase + s;
        xa3 = x + xids[baseA + 3] * KDIM + kbase + s;
        const int baseB = (dual ? c1 : c0) * RDIM + r0;
        xb0 = x + xids[baseB + 0] * KDIM + kbase + s;
        xb1 = x + xids[baseB + 1] * KDIM + kbase + s;
        xb2 = x + xids[baseB + 2] * KDIM + kbase + s;
        xb3 = x + xids[baseB + 3] * KDIM + kbase + s;
    }

    // A[w][k][r]; this block's 32-r window, k-half slice
    const float* __restrict__ Ab =
        A + (size_t)wid * KDIM * RDIM + (size_t)kbase * RDIM + rbase;

    uint32_t as_u32[2], mb_u32[2];
    {
        uint32_t a0;
        asm("{ .reg .u64 t; cvta.to.shared.u64 t, %1; cvt.u32.u64 %0, t; }"
            : "=r"(a0) : "l"(&as[0][0]));
        as_u32[0] = a0;
        asm("{ .reg .u64 t; cvta.to.shared.u64 t, %1; cvt.u32.u64 %0, t; }"
            : "=r"(a0) : "l"(&as[1][0]));
        as_u32[1] = a0;
        asm("{ .reg .u64 t; cvta.to.shared.u64 t, %1; cvt.u32.u64 %0, t; }"
            : "=r"(a0) : "l"(&mbar[0]));
        mb_u32[0] = a0;
        mb_u32[1] = a0 + 8;
    }

    if (tid == 0) {
        asm volatile("mbarrier.init.shared::cta.b64 [%0], 1;" :: "r"(mb_u32[0]) : "memory");
        asm volatile("mbarrier.init.shared::cta.b64 [%0], 1;" :: "r"(mb_u32[1]) : "memory");
    }
    __syncthreads();

    const float* srcp = Ab + (size_t)tid * RDIM;     // +32 KB per chunk
    const uint32_t dstA = as_u32[0] + tid * (ASTRIDE * 4);
    const uint32_t dstB = as_u32[1] + tid * (ASTRIDE * 4);

    // ---- prologue: chunk 0 -> buf 0 ----
    if (tid == 0) {
        asm volatile("mbarrier.arrive.expect_tx.shared::cta.b64 _, [%0], %1;"
                     :: "r"(mb_u32[0]), "r"((uint32_t)CHUNK_TX) : "memory");
    }
    if (tid < KC) {
        asm volatile(
            "cp.async.bulk.shared::cluster.global.mbarrier::complete_tx::bytes "
            "[%0], [%1], %2, [%3];"
            :: "r"(dstA), "l"(srcp), "r"(128u), "r"(mb_u32[0]) : "memory");
    }
    srcp += KC * RDIM;

    float a0 = 0.f, a1 = 0.f, a2 = 0.f, a3 = 0.f;
    float b0 = 0.f, b1 = 0.f, b2 = 0.f, b3 = 0.f;
    int ph0 = 0, ph1 = 0;

    for (int ch = 0; ch < NCH; ++ch) {
        const int b = ch & 1;

        // refill the other buffer (its readers finished before last iter's sync)
        if (ch + 1 < NCH) {
            const int nb = b ^ 1;
            if (tid == 0) {
                asm volatile("mbarrier.arrive.expect_tx.shared::cta.b64 _, [%0], %1;"
                             :: "r"(mb_u32[nb]), "r"((uint32_t)CHUNK_TX) : "memory");
            }
            if (tid < KC) {
                asm volatile(
                    "cp.async.bulk.shared::cluster.global.mbarrier::complete_tx::bytes "
                    "[%0], [%1], %2, [%3];"
                    :: "r"(nb ? dstB : dstA), "l"(srcp), "r"(128u), "r"(mb_u32[nb])
                    : "memory");
            }
            srcp += KC * RDIM;
        }

        // wait for this chunk (acquire orders the LDS below; HW-sleep wait)
        {
            const uint32_t mb = mb_u32[b];
            const uint32_t ph = (uint32_t)(b ? ph1 : ph0);
            uint32_t done;
            do {
                asm volatile(
                    "{ .reg .pred p; "
                    "mbarrier.try_wait.parity.acquire.cta.shared::cta.b64 p, [%1], %2, 0x989680; "
                    "selp.b32 %0, 1, 0, p; }"
                    : "=r"(done) : "r"(mb), "r"(ph) : "memory");
            } while (!done);
            if (b) ph1 ^= 1; else ph0 ^= 1;
        }

        const float* asb = &as[b][0];
        if (dual) {
            #pragma unroll
            for (int i = 0; i < 4; ++i) {
                const int kl = s + 32 * i;
                const float4 av =
                    *reinterpret_cast<const float4*>(&asb[kl * ASTRIDE + 4 * q]);
                a0 += xa0[32 * i] * av.x;
                a1 += xa1[32 * i] * av.y;
                a2 += xa2[32 * i] * av.z;
                a3 += xa3[32 * i] * av.w;
                b0 += xb0[32 * i] * av.x;
                b1 += xb1[32 * i] * av.y;
                b2 += xb2[32 * i] * av.z;
                b3 += xb3[32 * i] * av.w;
            }
        } else {
            #pragma unroll
            for (int i = 0; i < 4; ++i) {
                const int kl = s + 32 * i;
                const float4 av =
                    *reinterpret_cast<const float4*>(&asb[kl * ASTRIDE + 4 * q]);
                a0 += xa0[32 * i] * av.x;
                a1 += xa1[32 * i] * av.y;
                a2 += xa2[32 * i] * av.z;
                a3 += xa3[32 * i] * av.w;
            }
        }
        xa0 += KC; xa1 += KC; xa2 += KC; xa3 += KC;
        xb0 += KC; xb1 += KC; xb2 += KC; xb3 += KC;

        if (ch + 1 < NCH) __syncthreads();   // readers done -> refill safe
    }

    // reduce over the 32 lanes (k) within each warp
    #pragma unroll
    for (int off = 16; off > 0; off >>= 1) {
        a0 += __shfl_xor_sync(0xffffffffu, a0, off);
        a1 += __shfl_xor_sync(0xffffffffu, a1, off);
        a2 += __shfl_xor_sync(0xffffffffu, a2, off);
        a3 += __shfl_xor_sync(0xffffffffu, a3, off);
        b0 += __shfl_xor_sync(0xffffffffu, b0, off);
        b1 += __shfl_xor_sync(0xffffffffu, b1, off);
        b2 += __shfl_xor_sync(0xffffffffu, b2, off);
        b3 += __shfl_xor_sync(0xffffffffu, b3, off);
    }
    // exactly two k-half partials per element; 2-operand fp add is commutative
    // -> deterministic. REDG.F32, per-warp-distinct addresses.
    if (s == 0) {
        float* oa = &out[c0 * RDIM + r0];
        atomicAdd(oa + 0, a0);
        atomicAdd(oa + 1, a1);
        atomicAdd(oa + 2, a2);
        atomicAdd(oa + 3, a3);
        if (dual) {
            float* ob = &out[c1 * RDIM + r0];
            atomicAdd(ob + 0, b0);
            atomicAdd(ob + 1, b1);
            atomicAdd(ob + 2, b2);
            atomicAdd(ob + 3, b3);
        }
    }
}

extern "C" void kernel_launch(void* const* d_in, const int* in_sizes, int n_in,
                              void* d_out, int out_size)
{
    const float* x    = (const float*)d_in[0];   // [512,1,4096] f32
    const int*   xids = (const int*)  d_in[1];   // [20480] i32
    const int*   wids = (const int*)  d_in[2];   // [320] i32
    const float* A    = (const float*)d_in[3];   // [80,4096,64] f32
    float*       out  = (float*)d_out;           // [320,1,64] f32

    const int C = in_sizes[2];                   // COMBINED_BS (320)
    prep_groups<<<1, CDIM>>>(wids, C);
    zero_out<<<(CDIM * RDIM) / 256, 256>>>(out);
    dim3 grid(CDIM, 2, 2);                       // (max groups, r-half, k-half)
    lora_gather_dot_kernel<<<grid, 256>>>(x, xids, wids, A, out);
}

// round 15
// speedup vs baseline: 2.3922x; 1.4189x over previous
#include <cuda_runtime.h>
#include <cuda.h>
#include <cuda_bf16.h>
#include <cstdint>

#define KDIM 4096
#define KHALF (KDIM / 2)        // 2048 k per block (k-split)
#define RDIM 64
#define NWID 80
#define CDIM 320
#define KC 128                  // k rows per chunk
#define NCH (KHALF / KC)        // 16 chunks per block
#define TILE_B (KC * 128)       // stage bytes: 128 rows x 128 B = 16 KB
#define NSTAGE 3
#define DYN_SMEM (NSTAGE * TILE_B + 1024)   // + slack for 1024-B alignment

// Pair tables: groups of <=2 c-indices sharing a wid (c1 = -1 for singleton).
__device__ int g_gc0[CDIM];
__device__ int g_gc1[CDIM];
__device__ int g_ngroups;

// Fused prep + zero. grid = 65 x 320 threads:
//   block 0: pairing (atomicAdd rank; pairing order nondeterministic but each
//            c's output is partner-independent -> deterministic output).
//   blocks 1..64: zero out[] (poisoned 0xAA; k-split partials atomicAdd later).
__global__ void prep_and_zero(const int* __restrict__ wids, float* __restrict__ out)
{
    const int t = threadIdx.x;
    if (blockIdx.x > 0) {
        out[(blockIdx.x - 1) * 320 + t] = 0.f;
        return;
    }
    __shared__ int cnt[NWID];
    __shared__ int hbase[NWID];
    if (t < NWID) cnt[t] = 0;
    __syncthreads();
    int w = 0, r = 0;
    if (t < CDIM) { w = wids[t]; r = atomicAdd(&cnt[w], 1); }
    __syncthreads();
    if (t < NWID) {              // parallel exclusive prefix of halved counts
        int a = 0;
        for (int i = 0; i < t; ++i) a += (cnt[i] + 1) >> 1;
        hbase[t] = a;
        if (t == NWID - 1) g_ngroups = a + ((cnt[t] + 1) >> 1);
    }
    __syncthreads();
    if (t < CDIM) {
        const int grp = hbase[w] + (r >> 1);
        if (r & 1) {
            g_gc1[grp] = t;
        } else {
            g_gc0[grp] = t;
            if (r == cnt[w] - 1) g_gc1[grp] = -1;   // odd tail -> singleton
        }
    }
}

// out[c,r] = sum_k x[xids[c*64+r], k] * A[wids[c], k, r]
//
// Block = (pair group, r-half, k-half). 256 threads = 8 warps.
//   warp q owns r-quad r0 = rh*32+4q; lane s owns k = {s,s+32,s+64,s+96}/chunk.
//   Each thread accumulates BOTH paired c's against the same smem A tile.
// A: ONE 2D TMA tile load per chunk (box 32 floats x 128 rows, SW128) into a
//    3-deep smem ring; two loads in flight during compute. Swizzled read:
//    row kl at 16B column (q ^ (kl&7)); kl&7 == s&7 -> constant per thread,
//    8 distinct banks per quarter-warp phase -> conflict-free LDS.128.
// Exactly 2 k-half partials per out element via atomicAdd: 2-operand fp add is
// commutative -> bitwise deterministic.
__global__ void __launch_bounds__(256, 4) lora_gather_dot_kernel(
    const __grid_constant__ CUtensorMap tmap,
    const float* __restrict__ x,
    const int*   __restrict__ xids,
    const int*   __restrict__ wids,
    float*       __restrict__ out)
{
    if ((int)blockIdx.x >= g_ngroups) return;   // uniform per block

    extern __shared__ char dsm_raw[];
    __shared__ __align__(8) unsigned long long mbar[NSTAGE];

    const int g   = blockIdx.x;
    const int rh  = blockIdx.y;
    const int kz  = blockIdx.z;
    const int tid = threadIdx.x;
    const int q   = tid >> 5;
    const int s   = tid & 31;

    const int c0   = g_gc0[g];
    const int c1   = g_gc1[g];
    const bool dual = (c1 >= 0);

    const int wid   = wids[c0];
    const int rbase = rh * 32;
    const int r0    = rbase + 4 * q;
    const int kbase = kz * KHALF;

    // 1024-B aligned ring base (TMA SW128 dst alignment requirement)
    uint32_t ring_u32;
    {
        uint32_t a;
        asm("{ .reg .u64 t; cvta.to.shared.u64 t, %1; cvt.u32.u64 %0, t; }"
            : "=r"(a) : "l"(dsm_raw));
        ring_u32 = (a + 1023u) & ~1023u;
    }
    char* ring = dsm_raw + (ring_u32 -
        [] (const char* p) { uint32_t a;
            asm("{ .reg .u64 t; cvta.to.shared.u64 t, %1; cvt.u32.u64 %0, t; }"
                : "=r"(a) : "l"(p));
            return a; } (dsm_raw));

    uint32_t mb_u32[NSTAGE];
    {
        uint32_t a;
        asm("{ .reg .u64 t; cvta.to.shared.u64 t, %1; cvt.u32.u64 %0, t; }"
            : "=r"(a) : "l"(&mbar[0]));
        mb_u32[0] = a; mb_u32[1] = a + 8; mb_u32[2] = a + 16;
    }

    // x row pointers (pre-offset by lane s and k-half) for both c's tokens
    const float *xa0, *xa1, *xa2, *xa3, *xb0, *xb1, *xb2, *xb3;
    {
        const int baseA = c0 * RDIM + r0;
        xa0 = x + xids[baseA + 0] * KDIM + kbase + s;
        xa1 = x + xids[baseA + 1] * KDIM + kbase + s;
        xa2 = x + xids[baseA + 2] * KDIM + kbase + s;
        xa3 = x + xids[baseA + 3] * KDIM + kbase + s;
        const int baseB = (dual ? c1 : c0) * RDIM + r0;
        xb0 = x + xids[baseB + 0] * KDIM + kbase + s;
        xb1 = x + xids[baseB + 1] * KDIM + kbase + s;
        xb2 = x + xids[baseB + 2] * KDIM + kbase + s;
        xb3 = x + xids[baseB + 3] * KDIM + kbase + s;
    }

    if (tid == 0) {
        #pragma unroll
        for (int i = 0; i < NSTAGE; ++i)
            asm volatile("mbarrier.init.shared::cta.b64 [%0], 1;"
                         :: "r"(mb_u32[i]) : "memory");
    }
    __syncthreads();

    // A global row index of chunk chk: wid*KDIM + kbase + chk*KC ; x-coord = rbase
    const int row0 = wid * KDIM + kbase;

    // ---- prologue: issue chunks 0,1 into slots 0,1 ----
    if (tid == 0) {
        #pragma unroll
        for (int i = 0; i < 2; ++i) {
            asm volatile("mbarrier.arrive.expect_tx.shared::cta.b64 _, [%0], %1;"
                         :: "r"(mb_u32[i]), "r"((uint32_t)TILE_B) : "memory");
            asm volatile(
                "cp.async.bulk.tensor.2d.shared::cta.global.tile.mbarrier::complete_tx::bytes "
                "[%0], [%1, {%2, %3}], [%4];"
                :: "r"(ring_u32 + i * TILE_B), "l"(&tmap),
                   "r"(rbase), "r"(row0 + i * KC), "r"(mb_u32[i]) : "memory");
        }
    }

    float a0 = 0.f, a1 = 0.f, a2 = 0.f, a3 = 0.f;
    float b0 = 0.f, b1 = 0.f, b2 = 0.f, b3 = 0.f;
    int ph[NSTAGE] = {0, 0, 0};

    // per-thread constant swizzled column + row offset within a tile
    const int tile_off = s * 128 + (((q ^ (s & 7)) << 4));

    for (int ch = 0; ch < NCH; ++ch) {
        const int sl = ch % NSTAGE;

        // issue chunk ch+2 into slot (ch+2)%NSTAGE: its readers finished at
        // iter ch-1, separated by that iter's __syncthreads.
        if (tid == 0 && ch + 2 < NCH) {
            const int il = (ch + 2) % NSTAGE;
            asm volatile("mbarrier.arrive.expect_tx.shared::cta.b64 _, [%0], %1;"
                         :: "r"(mb_u32[il]), "r"((uint32_t)TILE_B) : "memory");
            asm volatile(
                "cp.async.bulk.tensor.2d.shared::cta.global.tile.mbarrier::complete_tx::bytes "
                "[%0], [%1, {%2, %3}], [%4];"
                :: "r"(ring_u32 + il * TILE_B), "l"(&tmap),
                   "r"(rbase), "r"(row0 + (ch + 2) * KC), "r"(mb_u32[il]) : "memory");
        }

        // wait for this chunk (acquire orders the LDS below; HW-sleep wait)
        {
            uint32_t done;
            do {
                asm volatile(
                    "{ .reg .pred p; "
                    "mbarrier.try_wait.parity.acquire.cta.shared::cta.b64 p, [%1], %2, 0x989680; "
                    "selp.b32 %0, 1, 0, p; }"
                    : "=r"(done) : "r"(mb_u32[sl]), "r"((uint32_t)ph[sl]) : "memory");
            } while (!done);
            ph[sl] ^= 1;
        }

        const char* sb = ring + sl * TILE_B + tile_off;
        if (dual) {
            #pragma unroll
            for (int i = 0; i < 4; ++i) {
                const float4 av = *reinterpret_cast<const float4*>(sb + i * 4096);
                a0 += xa0[32 * i] * av.x;
                a1 += xa1[32 * i] * av.y;
                a2 += xa2[32 * i] * av.z;
                a3 += xa3[32 * i] * av.w;
                b0 += xb0[32 * i] * av.x;
                b1 += xb1[32 * i] * av.y;
                b2 += xb2[32 * i] * av.z;
                b3 += xb3[32 * i] * av.w;
            }
        } else {
            #pragma unroll
            for (int i = 0; i < 4; ++i) {
                const float4 av = *reinterpret_cast<const float4*>(sb + i * 4096);
                a0 += xa0[32 * i] * av.x;
                a1 += xa1[32 * i] * av.y;
                a2 += xa2[32 * i] * av.z;
                a3 += xa3[32 * i] * av.w;
            }
        }
        xa0 += KC; xa1 += KC; xa2 += KC; xa3 += KC;
        xb0 += KC; xb1 += KC; xb2 += KC; xb3 += KC;

        if (ch + 1 < NCH) __syncthreads();   // readers of slot done -> refill safe
    }

    // reduce over the 32 lanes (k) within each warp
    #pragma unroll
    for (int off = 16; off > 0; off >>= 1) {
        a0 += __shfl_xor_sync(0xffffffffu, a0, off);
        a1 += __shfl_xor_sync(0xffffffffu, a1, off);
        a2 += __shfl_xor_sync(0xffffffffu, a2, off);
        a3 += __shfl_xor_sync(0xffffffffu, a3, off);
        b0 += __shfl_xor_sync(0xffffffffu, b0, off);
        b1 += __shfl_xor_sync(0xffffffffu, b1, off);
        b2 += __shfl_xor_sync(0xffffffffu, b2, off);
        b3 += __shfl_xor_sync(0xffffffffu, b3, off);
    }
    if (s == 0) {
        float* oa = &out[c0 * RDIM + r0];
        atomicAdd(oa + 0, a0);
        atomicAdd(oa + 1, a1);
        atomicAdd(oa + 2, a2);
        atomicAdd(oa + 3, a3);
        if (dual) {
            float* ob = &out[c1 * RDIM + r0];
            atomicAdd(ob + 0, b0);
            atomicAdd(ob + 1, b1);
            atomicAdd(ob + 2, b2);
            atomicAdd(ob + 3, b3);
        }
    }
}

extern "C" void kernel_launch(void* const* d_in, const int* in_sizes, int n_in,
                              void* d_out, int out_size)
{
    const float* x    = (const float*)d_in[0];   // [512,1,4096] f32
    const int*   xids = (const int*)  d_in[1];   // [20480] i32
    const int*   wids = (const int*)  d_in[2];   // [320] i32
    const float* A    = (const float*)d_in[3];   // [80,4096,64] f32
    float*       out  = (float*)d_out;           // [320,1,64] f32

    // Build the A tensor map (2D: 64 floats wide, NWID*KDIM rows, 256-B row
    // stride; box 32x128; SW128). Host driver call via cudart entry point —
    // no allocation, no stream op; runs fine under graph capture.
    typedef CUresult (*EncodeFn)(
        CUtensorMap*, CUtensorMapDataType, cuuint32_t, void*,
        const cuuint64_t*, const cuuint64_t*, const cuuint32_t*, const cuuint32_t*,
        CUtensorMapInterleave, CUtensorMapSwizzle, CUtensorMapL2promotion,
        CUtensorMapFloatOOBfill);
    void* fp = nullptr;
    cudaDriverEntryPointQueryResult qr;
    cudaGetDriverEntryPointByVersion("cuTensorMapEncodeTiled", &fp, 12000,
                                     cudaEnableDefault, &qr);
    CUtensorMap tmap;
    {
        EncodeFn enc = (EncodeFn)fp;
        cuuint64_t dims[2]    = {RDIM, (cuuint64_t)NWID * KDIM};
        cuuint64_t strides[1] = {RDIM * sizeof(float)};          // 256 B
        cuuint32_t box[2]     = {32, KC};                        // 128 B x 128 rows
        cuuint32_t estr[2]    = {1, 1};
        enc(&tmap, CU_TENSOR_MAP_DATA_TYPE_FLOAT32, 2, (void*)A,
            dims, strides, box, estr,
            CU_TENSOR_MAP_INTERLEAVE_NONE, CU_TENSOR_MAP_SWIZZLE_128B,
            CU_TENSOR_MAP_L2_PROMOTION_L2_128B, CU_TENSOR_MAP_FLOAT_OOB_FILL_NONE);
    }

    cudaFuncSetAttribute(lora_gather_dot_kernel,
                         cudaFuncAttributeMaxDynamicSharedMemorySize, DYN_SMEM);

    prep_and_zero<<<65, CDIM>>>(wids, out);
    dim3 grid(CDIM, 2, 2);                       // (max groups, r-half, k-half)
    lora_gather_dot_kernel<<<grid, 256, DYN_SMEM>>>(tmap, x, xids, wids, out);
}